// round 5
// baseline (speedup 1.0000x reference)
#include <cuda_runtime.h>
#include <cstdint>

#define T_LEN 2048
#define BATCH 16
#define I_DIM 512
#define H_DIM 512
#define IH    1024

typedef unsigned long long ull;

// ---------------------------------------------------------------------------
// helpers
// ---------------------------------------------------------------------------
__device__ __forceinline__ ull f32x2_fma(ull a, ull b, ull c) {
    ull d;
    asm("fma.rn.f32x2 %0, %1, %2, %3;" : "=l"(d) : "l"(a), "l"(b), "l"(c));
    return d;
}
__device__ __forceinline__ ull f32x2_add(ull a, ull b) {
    ull d;
    asm("add.rn.f32x2 %0, %1, %2;" : "=l"(d) : "l"(a), "l"(b));
    return d;
}
__device__ __forceinline__ uint32_t smem_u32(const void* p) {
    uint32_t a;
    asm("{ .reg .u64 t; cvta.to.shared.u64 t, %1; cvt.u32.u64 %0, t; }"
        : "=r"(a) : "l"(p));
    return a;
}
__device__ __forceinline__ uint32_t mapa_u32(uint32_t laddr, uint32_t rank) {
    uint32_t r;
    asm("mapa.shared::cluster.u32 %0, %1, %2;" : "=r"(r) : "r"(laddr), "r"(rank));
    return r;
}
__device__ __forceinline__ void mbar_init(uint32_t mb, uint32_t cnt) {
    asm volatile("mbarrier.init.shared.b64 [%0], %1;" :: "r"(mb), "r"(cnt) : "memory");
}
__device__ __forceinline__ void mbar_arrive_expect_tx(uint32_t mb, uint32_t bytes) {
    asm volatile("mbarrier.arrive.expect_tx.shared.b64 _, [%0], %1;"
                 :: "r"(mb), "r"(bytes) : "memory");
}
__device__ __forceinline__ void mbar_wait(uint32_t mb, uint32_t parity) {
    uint32_t done;
    asm volatile(
        "{\n\t.reg .pred p;\n\t"
        "mbarrier.try_wait.parity.acquire.cta.shared::cta.b64 p, [%1], %2;\n\t"
        "selp.b32 %0, 1, 0, p;\n\t}"
        : "=r"(done) : "r"(mb), "r"(parity) : "memory");
    if (!done) {
        asm volatile(
            "{\n\t.reg .pred P1;\n\t"
            "WAIT_LOOP_%=:\n\t"
            "mbarrier.try_wait.parity.acquire.cta.shared::cta.b64 P1, [%0], %1, 0x989680;\n\t"
            "@P1 bra.uni WAIT_DONE_%=;\n\t"
            "bra.uni WAIT_LOOP_%=;\n\t"
            "WAIT_DONE_%=:\n\t}"
            :: "r"(mb), "r"(parity) : "memory");
    }
}
// Bulk DSMEM copy: local SMEM -> peer CTA SMEM, completes on peer's mbarrier.
__device__ __forceinline__ void dsmem_bulk(uint32_t dst, uint32_t src,
                                           uint32_t bytes, uint32_t rmbar) {
    asm volatile(
        "cp.async.bulk.shared::cluster.shared::cta.mbarrier::complete_tx::bytes "
        "[%0], [%1], %2, [%3];"
        :: "r"(dst), "r"(src), "r"(bytes), "r"(rmbar) : "memory");
}
__device__ __forceinline__ void fence_proxy_async_cta() {
    asm volatile("fence.proxy.async.shared::cta;" ::: "memory");
}

// ---------------------------------------------------------------------------
// Kernel 1: x_proj = inputs @ w_xh^T + bias, written IN-PLACE into d_out
// ---------------------------------------------------------------------------
__global__ void __launch_bounds__(256)
xproj_gemm(const float* __restrict__ A, const float* __restrict__ W,
           const float* __restrict__ bias, float* __restrict__ C) {
    __shared__ __align__(16) float As[16][128];
    __shared__ __align__(16) float Bs[16][128];

    const int tid = threadIdx.x;
    const int m0 = blockIdx.y * 128;
    const int n0 = blockIdx.x * 128;
    const int tx = tid & 15;
    const int ty = tid >> 4;
    const int lr = tid >> 2;
    const int lc = (tid & 3) * 4;

    float acc[8][8];
#pragma unroll
    for (int i = 0; i < 8; i++)
#pragma unroll
        for (int j = 0; j < 8; j++) acc[i][j] = 0.f;

    for (int k0 = 0; k0 < 512; k0 += 16) {
#pragma unroll
        for (int s = 0; s < 2; s++) {
            int row = lr + s * 64;
            float4 va = *(const float4*)(A + (size_t)(m0 + row) * 512 + k0 + lc);
            As[lc + 0][row] = va.x; As[lc + 1][row] = va.y;
            As[lc + 2][row] = va.z; As[lc + 3][row] = va.w;
            float4 vb = *(const float4*)(W + (size_t)(n0 + row) * IH + 512 + k0 + lc);
            Bs[lc + 0][row] = vb.x; Bs[lc + 1][row] = vb.y;
            Bs[lc + 2][row] = vb.z; Bs[lc + 3][row] = vb.w;
        }
        __syncthreads();

#pragma unroll
        for (int kk = 0; kk < 16; kk++) {
            float4 a0 = *(const float4*)&As[kk][ty * 8];
            float4 a1 = *(const float4*)&As[kk][ty * 8 + 4];
            float4 b0 = *(const float4*)&Bs[kk][tx * 8];
            float4 b1 = *(const float4*)&Bs[kk][tx * 8 + 4];
            float af[8] = {a0.x, a0.y, a0.z, a0.w, a1.x, a1.y, a1.z, a1.w};
            float bf[8] = {b0.x, b0.y, b0.z, b0.w, b1.x, b1.y, b1.z, b1.w};
#pragma unroll
            for (int i = 0; i < 8; i++)
#pragma unroll
                for (int j = 0; j < 8; j++) acc[i][j] = fmaf(af[i], bf[j], acc[i][j]);
        }
        __syncthreads();
    }

    float bj[8];
#pragma unroll
    for (int j = 0; j < 8; j++) bj[j] = bias[n0 + tx * 8 + j];

#pragma unroll
    for (int i = 0; i < 8; i++) {
        int row = m0 + ty * 8 + i;
        float4 v0, v1;
        v0.x = acc[i][0] + bj[0]; v0.y = acc[i][1] + bj[1];
        v0.z = acc[i][2] + bj[2]; v0.w = acc[i][3] + bj[3];
        v1.x = acc[i][4] + bj[4]; v1.y = acc[i][5] + bj[5];
        v1.z = acc[i][6] + bj[6]; v1.w = acc[i][7] + bj[7];
        float4* cp = (float4*)(C + (size_t)row * 512 + n0 + tx * 8);
        cp[0] = v0;
        cp[1] = v1;
    }
}

// ---------------------------------------------------------------------------
// Kernel 2: sequential scan. 8-CTA cluster per batch. Weights in registers.
// Per step, each CTA stages its 64-value h fragment in SMEM and sends it to
// all 8 cluster CTAs via 8 bulk DSMEM copies (256 B each), completing on the
// receivers' mbarriers (expect_tx = 2048 B). No per-element remote stores.
// ---------------------------------------------------------------------------
__global__ void __cluster_dims__(8, 1, 1) __launch_bounds__(256, 1)
rnn_scan(const float* __restrict__ state, const float* __restrict__ W,
         float* __restrict__ outp, float* __restrict__ lastp) {
    __shared__ __align__(16) float h_buf[2][512];
    __shared__ __align__(16) float frag[2][64];
    __shared__ __align__(8) ull mbar[2];

    const int tid = threadIdx.x;
    const int cta = blockIdx.x;
    const int b   = cta >> 3;
    const int kg  = cta & 7;
    const int o   = tid >> 2;   // 0..63 local output row
    const int sub = tid & 3;    // 0..3 k-slice
    const int k   = kg * 64 + o;

    // 128 weights per thread in registers (64 packed f32x2).
    ull w[64];
    {
        const ull* wp = (const ull*)(W + (size_t)k * IH + sub * 128);
#pragma unroll
        for (int i = 0; i < 64; i++) w[i] = wp[i];
    }

    for (int j = tid; j < 512; j += 256) h_buf[0][j] = state[b * 512 + j];

    const uint32_t mb0 = smem_u32(&mbar[0]);
    const uint32_t mb1 = smem_u32(&mbar[1]);
    if (tid == 0) {
        mbar_init(mb0, 1);
        mbar_init(mb1, 1);
        mbar_arrive_expect_tx(mb0, 2048);  // receives fragments sent at t=1
        mbar_arrive_expect_tx(mb1, 2048);  // receives fragments sent at t=0
    }
    __syncthreads();
    // Cluster entry barrier: mbarriers must be live before any peer copy.
    asm volatile("barrier.cluster.arrive.aligned;" ::: "memory");
    asm volatile("barrier.cluster.wait.aligned;" ::: "memory");

    // Remote addresses: our fragment slot (h_buf[buf][kg*64]) and mbar on
    // each rank, per destination buffer.
    const uint32_t d0 = smem_u32(&h_buf[0][kg * 64]);
    const uint32_t d1 = smem_u32(&h_buf[1][kg * 64]);
    const uint32_t f0 = smem_u32(&frag[0][0]);
    const uint32_t f1 = smem_u32(&frag[1][0]);
    uint32_t rdst0 = 0, rdst1 = 0, rmb0 = 0, rmb1 = 0;
    if (tid < 8) {
        rdst0 = mapa_u32(d0, tid);
        rdst1 = mapa_u32(d1, tid);
        rmb0  = mapa_u32(mb0, tid);
        rmb1  = mapa_u32(mb1, tid);
    }

    size_t idx = ((size_t)b) * 512 + k;
    float xp_cur = (sub == 0) ? outp[idx] : 0.f;
    uint32_t par0 = 0, par1 = 0;

#define RNN_STEP(CUR, TT, MB_L, PAR, FRAG_SRC, RDST, RMB)                       \
    do {                                                                        \
        if ((TT) > 0) {                                                         \
            mbar_wait(MB_L, PAR);                                               \
            PAR ^= 1;                                                           \
            if (tid == 0 && (TT) + 2 < T_LEN)                                   \
                mbar_arrive_expect_tx(MB_L, 2048);                              \
        }                                                                       \
        float xp_next = 0.f;                                                    \
        if (sub == 0 && (TT) + 1 < T_LEN) xp_next = __ldg(outp + idx + 8192);   \
        const ulonglong2* hp = (const ulonglong2*)&h_buf[CUR][sub * 128];       \
        ull a0 = 0ull, a1 = 0ull, a2 = 0ull, a3 = 0ull;                         \
        _Pragma("unroll")                                                       \
        for (int jj = 0; jj < 8; jj++) {                                        \
            ulonglong2 v0 = hp[4 * jj + 0];                                     \
            ulonglong2 v1 = hp[4 * jj + 1];                                     \
            ulonglong2 v2 = hp[4 * jj + 2];                                     \
            ulonglong2 v3 = hp[4 * jj + 3];                                     \
            a0 = f32x2_fma(w[8 * jj + 0], v0.x, a0);                            \
            a1 = f32x2_fma(w[8 * jj + 1], v0.y, a1);                            \
            a2 = f32x2_fma(w[8 * jj + 2], v1.x, a2);                            \
            a3 = f32x2_fma(w[8 * jj + 3], v1.y, a3);                            \
            a0 = f32x2_fma(w[8 * jj + 4], v2.x, a0);                            \
            a1 = f32x2_fma(w[8 * jj + 5], v2.y, a1);                            \
            a2 = f32x2_fma(w[8 * jj + 6], v3.x, a2);                            \
            a3 = f32x2_fma(w[8 * jj + 7], v3.y, a3);                            \
        }                                                                       \
        ull s = f32x2_add(f32x2_add(a0, a1), f32x2_add(a2, a3));                \
        float lo, hi;                                                           \
        asm("mov.b64 {%0, %1}, %2;" : "=f"(lo), "=f"(hi) : "l"(s));             \
        float a = lo + hi;                                                      \
        a += __shfl_xor_sync(0xffffffffu, a, 1);                                \
        a += __shfl_xor_sync(0xffffffffu, a, 2);                                \
        if (sub == 0) {                                                         \
            float val = a + xp_cur;                                             \
            outp[idx] = val;                                                    \
            if ((TT) == T_LEN - 1) lastp[b * 512 + k] = val;                    \
            else                   frag[CUR][o] = val;                          \
        }                                                                       \
        if ((TT) != T_LEN - 1) {                                                \
            __syncthreads();                                                    \
            if (tid < 8) {                                                      \
                fence_proxy_async_cta();                                        \
                dsmem_bulk(RDST, FRAG_SRC, 256, RMB);                           \
            }                                                                   \
        }                                                                       \
        xp_cur = xp_next;                                                       \
        idx += 8192;                                                            \
    } while (0)

    for (int t = 0; t < T_LEN; t += 2) {
        RNN_STEP(0, t,     mb0, par0, f0, rdst1, rmb1);  // reads buf0, fills buf1
        RNN_STEP(1, t + 1, mb1, par1, f1, rdst0, rmb0);  // reads buf1, fills buf0
    }
#undef RNN_STEP

    // Keep CTAs alive until all in-flight transfers have landed.
    asm volatile("barrier.cluster.arrive.aligned;" ::: "memory");
    asm volatile("barrier.cluster.wait.aligned;" ::: "memory");
}

// ---------------------------------------------------------------------------
extern "C" void kernel_launch(void* const* d_in, const int* in_sizes, int n_in,
                              void* d_out, int out_size) {
    const float* inputs = (const float*)d_in[0];  // (T, B, I)
    const float* state  = (const float*)d_in[1];  // (B, H)
    const float* weight = (const float*)d_in[2];  // (H, I+H)
    const float* bias   = (const float*)d_in[3];  // (H,)
    float* outp  = (float*)d_out;                          // (T, B, H)
    float* lastp = outp + (size_t)T_LEN * BATCH * H_DIM;   // (B, H)

    dim3 ggrid(512 / 128, (T_LEN * BATCH) / 128);
    xproj_gemm<<<ggrid, 256>>>(inputs, weight, bias, outp);

    rnn_scan<<<BATCH * 8, 256>>>(state, weight, outp, lastp);
}

// round 6
// speedup vs baseline: 1.6330x; 1.6330x over previous
#include <cuda_runtime.h>
#include <cstdint>

#define T_LEN 2048
#define BATCH 16
#define I_DIM 512
#define H_DIM 512
#define IH    1024
#define B_PER 4            // batches per cluster
#define SLICE_PAD 132      // 128 floats + 16B pad -> conflict-free sub slices

typedef unsigned long long ull;

// ---------------------------------------------------------------------------
// helpers
// ---------------------------------------------------------------------------
__device__ __forceinline__ ull f32x2_fma(ull a, ull b, ull c) {
    ull d;
    asm("fma.rn.f32x2 %0, %1, %2, %3;" : "=l"(d) : "l"(a), "l"(b), "l"(c));
    return d;
}
__device__ __forceinline__ ull f32x2_add(ull a, ull b) {
    ull d;
    asm("add.rn.f32x2 %0, %1, %2;" : "=l"(d) : "l"(a), "l"(b));
    return d;
}
__device__ __forceinline__ uint32_t smem_u32(const void* p) {
    uint32_t a;
    asm("{ .reg .u64 t; cvta.to.shared.u64 t, %1; cvt.u32.u64 %0, t; }"
        : "=r"(a) : "l"(p));
    return a;
}
__device__ __forceinline__ uint32_t mapa_u32(uint32_t laddr, uint32_t rank) {
    uint32_t r;
    asm("mapa.shared::cluster.u32 %0, %1, %2;" : "=r"(r) : "r"(laddr), "r"(rank));
    return r;
}
__device__ __forceinline__ void mbar_init(uint32_t mb, uint32_t cnt) {
    asm volatile("mbarrier.init.shared.b64 [%0], %1;" :: "r"(mb), "r"(cnt) : "memory");
}
__device__ __forceinline__ void mbar_arrive_expect_tx(uint32_t mb, uint32_t bytes) {
    asm volatile("mbarrier.arrive.expect_tx.shared.b64 _, [%0], %1;"
                 :: "r"(mb), "r"(bytes) : "memory");
}
__device__ __forceinline__ void mbar_wait(uint32_t mb, uint32_t parity) {
    uint32_t done;
    asm volatile(
        "{\n\t.reg .pred p;\n\t"
        "mbarrier.try_wait.parity.acquire.cta.shared::cta.b64 p, [%1], %2;\n\t"
        "selp.b32 %0, 1, 0, p;\n\t}"
        : "=r"(done) : "r"(mb), "r"(parity) : "memory");
    if (!done) {
        asm volatile(
            "{\n\t.reg .pred P1;\n\t"
            "WAIT_LOOP_%=:\n\t"
            "mbarrier.try_wait.parity.acquire.cta.shared::cta.b64 P1, [%0], %1, 0x989680;\n\t"
            "@P1 bra.uni WAIT_DONE_%=;\n\t"
            "bra.uni WAIT_LOOP_%=;\n\t"
            "WAIT_DONE_%=:\n\t}"
            :: "r"(mb), "r"(parity) : "memory");
    }
}
__device__ __forceinline__ void dsmem_bulk(uint32_t dst, uint32_t src,
                                           uint32_t bytes, uint32_t rmbar) {
    asm volatile(
        "cp.async.bulk.shared::cluster.shared::cta.mbarrier::complete_tx::bytes "
        "[%0], [%1], %2, [%3];"
        :: "r"(dst), "r"(src), "r"(bytes), "r"(rmbar) : "memory");
}
__device__ __forceinline__ void fence_proxy_async_cta() {
    asm volatile("fence.proxy.async.shared::cta;" ::: "memory");
}

// ---------------------------------------------------------------------------
// Kernel 1: x_proj = inputs @ w_xh^T + bias, written IN-PLACE into d_out
// ---------------------------------------------------------------------------
__global__ void __launch_bounds__(256)
xproj_gemm(const float* __restrict__ A, const float* __restrict__ W,
           const float* __restrict__ bias, float* __restrict__ C) {
    __shared__ __align__(16) float As[16][128];
    __shared__ __align__(16) float Bs[16][128];

    const int tid = threadIdx.x;
    const int m0 = blockIdx.y * 128;
    const int n0 = blockIdx.x * 128;
    const int tx = tid & 15;
    const int ty = tid >> 4;
    const int lr = tid >> 2;
    const int lc = (tid & 3) * 4;

    float acc[8][8];
#pragma unroll
    for (int i = 0; i < 8; i++)
#pragma unroll
        for (int j = 0; j < 8; j++) acc[i][j] = 0.f;

    for (int k0 = 0; k0 < 512; k0 += 16) {
#pragma unroll
        for (int s = 0; s < 2; s++) {
            int row = lr + s * 64;
            float4 va = *(const float4*)(A + (size_t)(m0 + row) * 512 + k0 + lc);
            As[lc + 0][row] = va.x; As[lc + 1][row] = va.y;
            As[lc + 2][row] = va.z; As[lc + 3][row] = va.w;
            float4 vb = *(const float4*)(W + (size_t)(n0 + row) * IH + 512 + k0 + lc);
            Bs[lc + 0][row] = vb.x; Bs[lc + 1][row] = vb.y;
            Bs[lc + 2][row] = vb.z; Bs[lc + 3][row] = vb.w;
        }
        __syncthreads();

#pragma unroll
        for (int kk = 0; kk < 16; kk++) {
            float4 a0 = *(const float4*)&As[kk][ty * 8];
            float4 a1 = *(const float4*)&As[kk][ty * 8 + 4];
            float4 b0 = *(const float4*)&Bs[kk][tx * 8];
            float4 b1 = *(const float4*)&Bs[kk][tx * 8 + 4];
            float af[8] = {a0.x, a0.y, a0.z, a0.w, a1.x, a1.y, a1.z, a1.w};
            float bf[8] = {b0.x, b0.y, b0.z, b0.w, b1.x, b1.y, b1.z, b1.w};
#pragma unroll
            for (int i = 0; i < 8; i++)
#pragma unroll
                for (int j = 0; j < 8; j++) acc[i][j] = fmaf(af[i], bf[j], acc[i][j]);
        }
        __syncthreads();
    }

    float bj[8];
#pragma unroll
    for (int j = 0; j < 8; j++) bj[j] = bias[n0 + tx * 8 + j];

#pragma unroll
    for (int i = 0; i < 8; i++) {
        int row = m0 + ty * 8 + i;
        float4 v0, v1;
        v0.x = acc[i][0] + bj[0]; v0.y = acc[i][1] + bj[1];
        v0.z = acc[i][2] + bj[2]; v0.w = acc[i][3] + bj[3];
        v1.x = acc[i][4] + bj[4]; v1.y = acc[i][5] + bj[5];
        v1.z = acc[i][6] + bj[6]; v1.w = acc[i][7] + bj[7];
        float4* cp = (float4*)(C + (size_t)row * 512 + n0 + tx * 8);
        cp[0] = v0;
        cp[1] = v1;
    }
}

// ---------------------------------------------------------------------------
// Kernel 2: scan, 4 clusters x 8 CTAs, each cluster pipelines B_PER=4 batches.
// Weight slice (64x512) in registers, shared by all batches. Per superstep:
// round-robin  wait(bb) -> compute(bb) -> send(bb); each batch's DSMEM latency
// hides behind the other batches' compute. h slices padded to 132 floats for
// conflict-free broadcast LDS.
// ---------------------------------------------------------------------------
__global__ void __cluster_dims__(8, 1, 1) __launch_bounds__(256, 1)
rnn_scan(const float* __restrict__ state, const float* __restrict__ W,
         float* __restrict__ outp, float* __restrict__ lastp) {
    // [buffer][batch][slice][SLICE_PAD]
    __shared__ __align__(16) float h_buf[2][B_PER][4][SLICE_PAD];
    __shared__ __align__(16) float frag[2][B_PER][64];
    __shared__ __align__(8) ull mbar[2][B_PER];

    const int tid = threadIdx.x;
    const int cta = blockIdx.x;
    const int cl4 = (cta >> 3) * B_PER;  // first batch of this cluster
    const int kg  = cta & 7;             // cluster rank
    const int o   = tid >> 2;            // 0..63 local output row
    const int sub = tid & 3;             // 0..3 k-slice
    const int k   = kg * 64 + o;

    // 128 weights per thread in registers (64 packed f32x2), shared by batches.
    ull w[64];
    {
        const ull* wp = (const ull*)(W + (size_t)k * IH + sub * 128);
#pragma unroll
        for (int i = 0; i < 64; i++) w[i] = wp[i];
    }

    // Initial state into buffer 0 for each batch.
    for (int j = tid; j < B_PER * 512; j += 256) {
        int bb = j >> 9, e = j & 511;
        h_buf[0][bb][e >> 7][e & 127] = state[(cl4 + bb) * 512 + e];
    }

    const uint32_t mb_base = smem_u32(&mbar[0][0]);
    const uint32_t hb_base = smem_u32(&h_buf[0][0][0][0]);
    if (tid == 0) {
#pragma unroll
        for (int i = 0; i < 2 * B_PER; i++) {
            mbar_init(mb_base + i * 8, 1);
            mbar_arrive_expect_tx(mb_base + i * 8, 2048);
        }
    }
    __syncthreads();
    asm volatile("barrier.cluster.arrive.aligned;" ::: "memory");
    asm volatile("barrier.cluster.wait.aligned;" ::: "memory");

    // Remote base addresses for rank = tid (tid < 8).
    uint32_t rhb = 0, rmb = 0;
    if (tid < 8) {
        rhb = mapa_u32(hb_base, tid);
        rmb = mapa_u32(mb_base, tid);
    }
    // Byte offset of our fragment inside h_buf[bf][bb]: slice kg/2, half kg&1.
    const uint32_t frag_off = (uint32_t)(kg >> 1) * (SLICE_PAD * 4) + (kg & 1) * 256;
    const uint32_t hb_stride = B_PER * 4 * SLICE_PAD * 4;  // bytes per buffer
    const uint32_t hb_bstride = 4 * SLICE_PAD * 4;         // bytes per batch

    size_t idx = ((size_t)cl4) * 512 + k;  // t=0, batch cl4; +512 per batch
    float xp_cur[B_PER];
#pragma unroll
    for (int bb = 0; bb < B_PER; bb++)
        xp_cur[bb] = (sub == 0) ? outp[idx + bb * 512] : 0.f;
    uint32_t par0 = 0, par1 = 0;

#define RNN_SUPER(CUR, NXT, TT, PAR)                                            \
    do {                                                                        \
        _Pragma("unroll")                                                       \
        for (int bb = 0; bb < B_PER; bb++) {                                    \
            const uint32_t mb_l = mb_base + ((CUR) * B_PER + bb) * 8;           \
            if ((TT) > 0) {                                                     \
                mbar_wait(mb_l, PAR);                                           \
                if (tid == 0 && (TT) + 2 < T_LEN)                               \
                    mbar_arrive_expect_tx(mb_l, 2048);                          \
            }                                                                   \
            float xp_next = 0.f;                                                \
            if (sub == 0 && (TT) + 1 < T_LEN)                                   \
                xp_next = __ldg(outp + idx + bb * 512 + 8192);                  \
            const ulonglong2* hp =                                              \
                (const ulonglong2*)&h_buf[CUR][bb][sub][0];                     \
            ull a0 = 0ull, a1 = 0ull, a2 = 0ull, a3 = 0ull;                     \
            _Pragma("unroll")                                                   \
            for (int jj = 0; jj < 8; jj++) {                                    \
                ulonglong2 v0 = hp[4 * jj + 0];                                 \
                ulonglong2 v1 = hp[4 * jj + 1];                                 \
                ulonglong2 v2 = hp[4 * jj + 2];                                 \
                ulonglong2 v3 = hp[4 * jj + 3];                                 \
                a0 = f32x2_fma(w[8 * jj + 0], v0.x, a0);                        \
                a1 = f32x2_fma(w[8 * jj + 1], v0.y, a1);                        \
                a2 = f32x2_fma(w[8 * jj + 2], v1.x, a2);                        \
                a3 = f32x2_fma(w[8 * jj + 3], v1.y, a3);                        \
                a0 = f32x2_fma(w[8 * jj + 4], v2.x, a0);                        \
                a1 = f32x2_fma(w[8 * jj + 5], v2.y, a1);                        \
                a2 = f32x2_fma(w[8 * jj + 6], v3.x, a2);                        \
                a3 = f32x2_fma(w[8 * jj + 7], v3.y, a3);                        \
            }                                                                   \
            ull s = f32x2_add(f32x2_add(a0, a1), f32x2_add(a2, a3));            \
            float lo, hi;                                                       \
            asm("mov.b64 {%0, %1}, %2;" : "=f"(lo), "=f"(hi) : "l"(s));         \
            float a = lo + hi;                                                  \
            a += __shfl_xor_sync(0xffffffffu, a, 1);                            \
            a += __shfl_xor_sync(0xffffffffu, a, 2);                            \
            if (sub == 0) {                                                     \
                float val = a + xp_cur[bb];                                     \
                outp[idx + bb * 512] = val;                                     \
                if ((TT) == T_LEN - 1) lastp[(cl4 + bb) * 512 + k] = val;       \
                else                   frag[CUR][bb][o] = val;                  \
            }                                                                   \
            xp_cur[bb] = xp_next;                                               \
            if ((TT) != T_LEN - 1) {                                            \
                __syncthreads();                                                \
                if (tid < 8) {                                                  \
                    fence_proxy_async_cta();                                    \
                    dsmem_bulk(rhb + (NXT) * hb_stride + bb * hb_bstride +      \
                                   frag_off,                                    \
                               smem_u32(&frag[CUR][bb][0]), 256,                \
                               rmb + ((NXT) * B_PER + bb) * 8);                 \
                }                                                               \
            }                                                                   \
        }                                                                       \
        if ((TT) > 0) PAR ^= 1;                                                 \
        idx += 8192;                                                            \
    } while (0)

    for (int t = 0; t < T_LEN; t += 2) {
        RNN_SUPER(0, 1, t,     par0);  // read buf0, fill buf1
        RNN_SUPER(1, 0, t + 1, par1);  // read buf1, fill buf0
    }
#undef RNN_SUPER

    asm volatile("barrier.cluster.arrive.aligned;" ::: "memory");
    asm volatile("barrier.cluster.wait.aligned;" ::: "memory");
}

// ---------------------------------------------------------------------------
extern "C" void kernel_launch(void* const* d_in, const int* in_sizes, int n_in,
                              void* d_out, int out_size) {
    const float* inputs = (const float*)d_in[0];  // (T, B, I)
    const float* state  = (const float*)d_in[1];  // (B, H)
    const float* weight = (const float*)d_in[2];  // (H, I+H)
    const float* bias   = (const float*)d_in[3];  // (H,)
    float* outp  = (float*)d_out;                          // (T, B, H)
    float* lastp = outp + (size_t)T_LEN * BATCH * H_DIM;   // (B, H)

    dim3 ggrid(512 / 128, (T_LEN * BATCH) / 128);
    xproj_gemm<<<ggrid, 256>>>(inputs, weight, bias, outp);

    rnn_scan<<<(BATCH / B_PER) * 8, 256>>>(state, weight, outp, lastp);
}

// round 7
// speedup vs baseline: 2.9846x; 1.8277x over previous
#include <cuda_runtime.h>
#include <cstdint>

#define T_LEN 2048
#define BATCH 16
#define I_DIM 512
#define H_DIM 512
#define IH    1024
#define B_PER 2            // batches per cluster (R6: 4 -> R7: 2)
#define SLICE_PAD 132      // 128 floats + 16B pad -> conflict-free sub slices

typedef unsigned long long ull;

// ---------------------------------------------------------------------------
// helpers
// ---------------------------------------------------------------------------
__device__ __forceinline__ ull f32x2_fma(ull a, ull b, ull c) {
    ull d;
    asm("fma.rn.f32x2 %0, %1, %2, %3;" : "=l"(d) : "l"(a), "l"(b), "l"(c));
    return d;
}
__device__ __forceinline__ ull f32x2_add(ull a, ull b) {
    ull d;
    asm("add.rn.f32x2 %0, %1, %2;" : "=l"(d) : "l"(a), "l"(b));
    return d;
}
__device__ __forceinline__ uint32_t smem_u32(const void* p) {
    uint32_t a;
    asm("{ .reg .u64 t; cvta.to.shared.u64 t, %1; cvt.u32.u64 %0, t; }"
        : "=r"(a) : "l"(p));
    return a;
}
__device__ __forceinline__ uint32_t mapa_u32(uint32_t laddr, uint32_t rank) {
    uint32_t r;
    asm("mapa.shared::cluster.u32 %0, %1, %2;" : "=r"(r) : "r"(laddr), "r"(rank));
    return r;
}
__device__ __forceinline__ void mbar_init(uint32_t mb, uint32_t cnt) {
    asm volatile("mbarrier.init.shared.b64 [%0], %1;" :: "r"(mb), "r"(cnt) : "memory");
}
__device__ __forceinline__ void mbar_arrive_expect_tx(uint32_t mb, uint32_t bytes) {
    asm volatile("mbarrier.arrive.expect_tx.shared.b64 _, [%0], %1;"
                 :: "r"(mb), "r"(bytes) : "memory");
}
__device__ __forceinline__ void mbar_wait(uint32_t mb, uint32_t parity) {
    uint32_t done;
    asm volatile(
        "{\n\t.reg .pred p;\n\t"
        "mbarrier.try_wait.parity.acquire.cta.shared::cta.b64 p, [%1], %2;\n\t"
        "selp.b32 %0, 1, 0, p;\n\t}"
        : "=r"(done) : "r"(mb), "r"(parity) : "memory");
    if (!done) {
        asm volatile(
            "{\n\t.reg .pred P1;\n\t"
            "WAIT_LOOP_%=:\n\t"
            "mbarrier.try_wait.parity.acquire.cta.shared::cta.b64 P1, [%0], %1, 0x989680;\n\t"
            "@P1 bra.uni WAIT_DONE_%=;\n\t"
            "bra.uni WAIT_LOOP_%=;\n\t"
            "WAIT_DONE_%=:\n\t}"
            :: "r"(mb), "r"(parity) : "memory");
    }
}
__device__ __forceinline__ void dsmem_bulk(uint32_t dst, uint32_t src,
                                           uint32_t bytes, uint32_t rmbar) {
    asm volatile(
        "cp.async.bulk.shared::cluster.shared::cta.mbarrier::complete_tx::bytes "
        "[%0], [%1], %2, [%3];"
        :: "r"(dst), "r"(src), "r"(bytes), "r"(rmbar) : "memory");
}
__device__ __forceinline__ void fence_proxy_async_cta() {
    asm volatile("fence.proxy.async.shared::cta;" ::: "memory");
}

// ---------------------------------------------------------------------------
// Kernel 1: x_proj = inputs @ w_xh^T + bias, written IN-PLACE into d_out
// ---------------------------------------------------------------------------
__global__ void __launch_bounds__(256)
xproj_gemm(const float* __restrict__ A, const float* __restrict__ W,
           const float* __restrict__ bias, float* __restrict__ C) {
    __shared__ __align__(16) float As[16][128];
    __shared__ __align__(16) float Bs[16][128];

    const int tid = threadIdx.x;
    const int m0 = blockIdx.y * 128;
    const int n0 = blockIdx.x * 128;
    const int tx = tid & 15;
    const int ty = tid >> 4;
    const int lr = tid >> 2;
    const int lc = (tid & 3) * 4;

    float acc[8][8];
#pragma unroll
    for (int i = 0; i < 8; i++)
#pragma unroll
        for (int j = 0; j < 8; j++) acc[i][j] = 0.f;

    for (int k0 = 0; k0 < 512; k0 += 16) {
#pragma unroll
        for (int s = 0; s < 2; s++) {
            int row = lr + s * 64;
            float4 va = *(const float4*)(A + (size_t)(m0 + row) * 512 + k0 + lc);
            As[lc + 0][row] = va.x; As[lc + 1][row] = va.y;
            As[lc + 2][row] = va.z; As[lc + 3][row] = va.w;
            float4 vb = *(const float4*)(W + (size_t)(n0 + row) * IH + 512 + k0 + lc);
            Bs[lc + 0][row] = vb.x; Bs[lc + 1][row] = vb.y;
            Bs[lc + 2][row] = vb.z; Bs[lc + 3][row] = vb.w;
        }
        __syncthreads();

#pragma unroll
        for (int kk = 0; kk < 16; kk++) {
            float4 a0 = *(const float4*)&As[kk][ty * 8];
            float4 a1 = *(const float4*)&As[kk][ty * 8 + 4];
            float4 b0 = *(const float4*)&Bs[kk][tx * 8];
            float4 b1 = *(const float4*)&Bs[kk][tx * 8 + 4];
            float af[8] = {a0.x, a0.y, a0.z, a0.w, a1.x, a1.y, a1.z, a1.w};
            float bf[8] = {b0.x, b0.y, b0.z, b0.w, b1.x, b1.y, b1.z, b1.w};
#pragma unroll
            for (int i = 0; i < 8; i++)
#pragma unroll
                for (int j = 0; j < 8; j++) acc[i][j] = fmaf(af[i], bf[j], acc[i][j]);
        }
        __syncthreads();
    }

    float bj[8];
#pragma unroll
    for (int j = 0; j < 8; j++) bj[j] = bias[n0 + tx * 8 + j];

#pragma unroll
    for (int i = 0; i < 8; i++) {
        int row = m0 + ty * 8 + i;
        float4 v0, v1;
        v0.x = acc[i][0] + bj[0]; v0.y = acc[i][1] + bj[1];
        v0.z = acc[i][2] + bj[2]; v0.w = acc[i][3] + bj[3];
        v1.x = acc[i][4] + bj[4]; v1.y = acc[i][5] + bj[5];
        v1.z = acc[i][6] + bj[6]; v1.w = acc[i][7] + bj[7];
        float4* cp = (float4*)(C + (size_t)row * 512 + n0 + tx * 8);
        cp[0] = v0;
        cp[1] = v1;
    }
}

// ---------------------------------------------------------------------------
// Kernel 2: scan, (BATCH/B_PER) clusters x 8 CTAs; each cluster pipelines
// B_PER batches round-robin per timestep: wait(bb) -> compute(bb) -> send(bb).
// Weight slice (64x512) in registers, shared across batches.
// ---------------------------------------------------------------------------
__global__ void __cluster_dims__(8, 1, 1) __launch_bounds__(256, 1)
rnn_scan(const float* __restrict__ state, const float* __restrict__ W,
         float* __restrict__ outp, float* __restrict__ lastp) {
    // [buffer][batch][slice][SLICE_PAD]
    __shared__ __align__(16) float h_buf[2][B_PER][4][SLICE_PAD];
    __shared__ __align__(16) float frag[2][B_PER][64];
    __shared__ __align__(8) ull mbar[2][B_PER];

    const int tid = threadIdx.x;
    const int cta = blockIdx.x;
    const int cl4 = (cta >> 3) * B_PER;  // first batch of this cluster
    const int kg  = cta & 7;             // cluster rank
    const int o   = tid >> 2;            // 0..63 local output row
    const int sub = tid & 3;             // 0..3 k-slice
    const int k   = kg * 64 + o;

    // 128 weights per thread in registers (64 packed f32x2), shared by batches.
    ull w[64];
    {
        const ull* wp = (const ull*)(W + (size_t)k * IH + sub * 128);
#pragma unroll
        for (int i = 0; i < 64; i++) w[i] = wp[i];
    }

    // Initial state into buffer 0 for each batch.
    for (int j = tid; j < B_PER * 512; j += 256) {
        int bb = j >> 9, e = j & 511;
        h_buf[0][bb][e >> 7][e & 127] = state[(cl4 + bb) * 512 + e];
    }

    const uint32_t mb_base = smem_u32(&mbar[0][0]);
    const uint32_t hb_base = smem_u32(&h_buf[0][0][0][0]);
    if (tid == 0) {
#pragma unroll
        for (int i = 0; i < 2 * B_PER; i++) {
            mbar_init(mb_base + i * 8, 1);
            mbar_arrive_expect_tx(mb_base + i * 8, 2048);
        }
    }
    __syncthreads();
    asm volatile("barrier.cluster.arrive.aligned;" ::: "memory");
    asm volatile("barrier.cluster.wait.aligned;" ::: "memory");

    // Remote base addresses for rank = tid (tid < 8).
    uint32_t rhb = 0, rmb = 0;
    if (tid < 8) {
        rhb = mapa_u32(hb_base, tid);
        rmb = mapa_u32(mb_base, tid);
    }
    // Byte offset of our fragment inside h_buf[bf][bb]: slice kg/2, half kg&1.
    const uint32_t frag_off = (uint32_t)(kg >> 1) * (SLICE_PAD * 4) + (kg & 1) * 256;
    const uint32_t hb_stride = B_PER * 4 * SLICE_PAD * 4;  // bytes per buffer
    const uint32_t hb_bstride = 4 * SLICE_PAD * 4;         // bytes per batch

    size_t idx = ((size_t)cl4) * 512 + k;  // t=0, batch cl4; +512 per batch
    float xp_cur[B_PER];
#pragma unroll
    for (int bb = 0; bb < B_PER; bb++)
        xp_cur[bb] = (sub == 0) ? outp[idx + bb * 512] : 0.f;
    uint32_t par0 = 0, par1 = 0;

#define RNN_SUPER(CUR, NXT, TT, PAR)                                            \
    do {                                                                        \
        _Pragma("unroll")                                                       \
        for (int bb = 0; bb < B_PER; bb++) {                                    \
            const uint32_t mb_l = mb_base + ((CUR) * B_PER + bb) * 8;           \
            if ((TT) > 0) {                                                     \
                mbar_wait(mb_l, PAR);                                           \
                if (tid == 0 && (TT) + 2 < T_LEN)                               \
                    mbar_arrive_expect_tx(mb_l, 2048);                          \
            }                                                                   \
            float xp_next = 0.f;                                                \
            if (sub == 0 && (TT) + 1 < T_LEN)                                   \
                xp_next = __ldg(outp + idx + bb * 512 + 8192);                  \
            const ulonglong2* hp =                                              \
                (const ulonglong2*)&h_buf[CUR][bb][sub][0];                     \
            ull a0 = 0ull, a1 = 0ull, a2 = 0ull, a3 = 0ull;                     \
            _Pragma("unroll")                                                   \
            for (int jj = 0; jj < 8; jj++) {                                    \
                ulonglong2 v0 = hp[4 * jj + 0];                                 \
                ulonglong2 v1 = hp[4 * jj + 1];                                 \
                ulonglong2 v2 = hp[4 * jj + 2];                                 \
                ulonglong2 v3 = hp[4 * jj + 3];                                 \
                a0 = f32x2_fma(w[8 * jj + 0], v0.x, a0);                        \
                a1 = f32x2_fma(w[8 * jj + 1], v0.y, a1);                        \
                a2 = f32x2_fma(w[8 * jj + 2], v1.x, a2);                        \
                a3 = f32x2_fma(w[8 * jj + 3], v1.y, a3);                        \
                a0 = f32x2_fma(w[8 * jj + 4], v2.x, a0);                        \
                a1 = f32x2_fma(w[8 * jj + 5], v2.y, a1);                        \
                a2 = f32x2_fma(w[8 * jj + 6], v3.x, a2);                        \
                a3 = f32x2_fma(w[8 * jj + 7], v3.y, a3);                        \
            }                                                                   \
            ull s = f32x2_add(f32x2_add(a0, a1), f32x2_add(a2, a3));            \
            float lo, hi;                                                       \
            asm("mov.b64 {%0, %1}, %2;" : "=f"(lo), "=f"(hi) : "l"(s));         \
            float a = lo + hi;                                                  \
            a += __shfl_xor_sync(0xffffffffu, a, 1);                            \
            a += __shfl_xor_sync(0xffffffffu, a, 2);                            \
            if (sub == 0) {                                                     \
                float val = a + xp_cur[bb];                                     \
                outp[idx + bb * 512] = val;                                     \
                if ((TT) == T_LEN - 1) lastp[(cl4 + bb) * 512 + k] = val;       \
                else                   frag[CUR][bb][o] = val;                  \
            }                                                                   \
            xp_cur[bb] = xp_next;                                               \
            if ((TT) != T_LEN - 1) {                                            \
                __syncthreads();                                                \
                if (tid < 8) {                                                  \
                    fence_proxy_async_cta();                                    \
                    dsmem_bulk(rhb + (NXT) * hb_stride + bb * hb_bstride +      \
                                   frag_off,                                    \
                               smem_u32(&frag[CUR][bb][0]), 256,                \
                               rmb + ((NXT) * B_PER + bb) * 8);                 \
                }                                                               \
            }                                                                   \
        }                                                                       \
        if ((TT) > 0) PAR ^= 1;                                                 \
        idx += 8192;                                                            \
    } while (0)

    for (int t = 0; t < T_LEN; t += 2) {
        RNN_SUPER(0, 1, t,     par0);  // read buf0, fill buf1
        RNN_SUPER(1, 0, t + 1, par1);  // read buf1, fill buf0
    }
#undef RNN_SUPER

    asm volatile("barrier.cluster.arrive.aligned;" ::: "memory");
    asm volatile("barrier.cluster.wait.aligned;" ::: "memory");
}

// ---------------------------------------------------------------------------
extern "C" void kernel_launch(void* const* d_in, const int* in_sizes, int n_in,
                              void* d_out, int out_size) {
    const float* inputs = (const float*)d_in[0];  // (T, B, I)
    const float* state  = (const float*)d_in[1];  // (B, H)
    const float* weight = (const float*)d_in[2];  // (H, I+H)
    const float* bias   = (const float*)d_in[3];  // (H,)
    float* outp  = (float*)d_out;                          // (T, B, H)
    float* lastp = outp + (size_t)T_LEN * BATCH * H_DIM;   // (B, H)

    dim3 ggrid(512 / 128, (T_LEN * BATCH) / 128);
    xproj_gemm<<<ggrid, 256>>>(inputs, weight, bias, outp);

    rnn_scan<<<(BATCH / B_PER) * 8, 256>>>(state, weight, outp, lastp);
}